// round 15
// baseline (speedup 1.0000x reference)
#include <cuda_runtime.h>
#include <cuda_bf16.h>
#include <cstdint>
#include <math.h>

#define BZ   2
#define SQ   2048
#define DM   1024
#define HH   16
#define HD   64
#define MR   (BZ*SQ)      // 4096 rows
#define K3   (3*DM)       // 3072 expanded-K

// ---- device-global scratch (no allocations allowed) ----
__device__ float g_v[(size_t)MR*DM];
__device__ __align__(16) __nv_bfloat16 g_x3[(size_t)MR*K3];
__device__ __align__(16) __nv_bfloat16 g_o3[(size_t)MR*K3];
__device__ __align__(16) __nv_bfloat16 g_wq3[(size_t)DM*K3];   // [N][K3]
__device__ __align__(16) __nv_bfloat16 g_wk3[(size_t)DM*K3];
__device__ __align__(16) __nv_bfloat16 g_wv3[(size_t)DM*K3];
__device__ __align__(16) __nv_bfloat16 g_wo3[(size_t)DM*K3];
__device__ __align__(16) __nv_bfloat16 g_q3[(size_t)BZ*HH*SQ*192];     // [bh][s][h|h|l]
__device__ __align__(16) __nv_bfloat16 g_k3[(size_t)BZ*HH*SQ*192];     // [bh][s][h|l|h]
__device__ __align__(16) __nv_bfloat16 g_v3t[(size_t)BZ*HH*HD*3*SQ];   // [bh][hd][Vh|Vl|Vh over s]

#define LDSM4(R0,R1,R2,R3,ADDR) \
    asm volatile("ldmatrix.sync.aligned.m8n8.x4.shared.b16 {%0,%1,%2,%3}, [%4];" \
                 : "=r"(R0), "=r"(R1), "=r"(R2), "=r"(R3) : "r"(ADDR))

// ---------------------------------------------------------------------------
// Split expansions (unchanged, proven)
// ---------------------------------------------------------------------------
__global__ __launch_bounds__(256) void expand_a3(
    const float* __restrict__ src, __nv_bfloat16* __restrict__ dst, int M, int K)
{
    int idx = blockIdx.x*256 + threadIdx.x;
    if (idx >= M*K) return;
    int m = idx / K, k = idx - m*K;
    float x = src[idx];
    __nv_bfloat16 h = __float2bfloat16(x);
    __nv_bfloat16 l = __float2bfloat16(x - __bfloat162float(h));
    size_t base = (size_t)m*3*K;
    dst[base + k] = h;
    dst[base + K + k] = h;
    dst[base + 2*K + k] = l;
}

__global__ __launch_bounds__(256) void expand_b3t(
    const float* __restrict__ src, __nv_bfloat16* __restrict__ dst, int K, int N)
{
    __shared__ float t[32][33];
    int tx = threadIdx.x & 31, ty = threadIdx.x >> 5;
    int nb = blockIdx.x * 32, kb = blockIdx.y * 32;
    #pragma unroll
    for (int i = 0; i < 4; i++)
        t[ty + 8*i][tx] = src[(size_t)(kb + ty + 8*i)*N + nb + tx];
    __syncthreads();
    #pragma unroll
    for (int i = 0; i < 4; i++) {
        int n = nb + ty + 8*i;
        int k = kb + tx;
        float x = t[tx][ty + 8*i];
        __nv_bfloat16 h = __float2bfloat16(x);
        __nv_bfloat16 l = __float2bfloat16(x - __bfloat162float(h));
        size_t base = (size_t)n*3*K;
        dst[base + k]       = h;
        dst[base + K + k]   = l;
        dst[base + 2*K + k] = h;
    }
}

__global__ __launch_bounds__(256) void expand_v3t(const float* __restrict__ src)
{
    __shared__ float t[32][33];
    int tx = threadIdx.x & 31, ty = threadIdx.x >> 5;
    int s0 = blockIdx.x * 32;
    int hd0 = blockIdx.y * 32;
    int bh = blockIdx.z;
    int b = bh >> 4, h = bh & 15;
    #pragma unroll
    for (int i = 0; i < 4; i++)
        t[ty + 8*i][tx] = src[(size_t)(b*SQ + s0 + ty + 8*i)*DM + h*64 + hd0 + tx];
    __syncthreads();
    #pragma unroll
    for (int i = 0; i < 4; i++) {
        int hd = hd0 + ty + 8*i;
        float x = t[tx][ty + 8*i];
        __nv_bfloat16 hh = __float2bfloat16(x);
        __nv_bfloat16 ll = __float2bfloat16(x - __bfloat162float(hh));
        size_t base = ((size_t)bh*HD + hd)*3*SQ;
        g_v3t[base + s0 + tx]        = hh;
        g_v3t[base + SQ + s0 + tx]   = ll;
        g_v3t[base + 2*SQ + s0 + tx] = hh;
    }
}

// ---------------------------------------------------------------------------
// bf16 HMMA GEMM v6: cp.async double-buffer + ldmatrix fragment loads.
// Layouts identical to v5 (stride 20 u32). mode 0 fp32; 1 split->g_q3 (x.125);
// 2 split->g_k3.
// ---------------------------------------------------------------------------
#define AST 20
#define STG (128*AST)

__global__ __launch_bounds__(256) void gemm_bf16(
    const __nv_bfloat16* __restrict__ A, const __nv_bfloat16* __restrict__ Bt,
    const float* __restrict__ bias, void* __restrict__ Cv,
    int M, int N, int Kx, int mode)
{
    __shared__ __align__(16) uint32_t As[2*STG];
    __shared__ __align__(16) uint32_t Bs[2*STG];

    int tid = threadIdx.x;
    int lane = tid & 31;
    int w = tid >> 5;
    int wm = w >> 2;
    int wn = w & 3;
    int g = lane >> 2;
    int t = lane & 3;
    int r8 = lane & 7;

    int m0 = blockIdx.y * 128;
    int n0 = blockIdx.x * 128;

    const int r0 = tid >> 2,  c0 = tid & 3;
    const int r1 = r0 + 64,   c1 = c0;

    const __nv_bfloat16* pA0 = A  + (size_t)(m0 + r0)*Kx + c0*8;
    const __nv_bfloat16* pA1 = A  + (size_t)(m0 + r1)*Kx + c1*8;
    const __nv_bfloat16* pB0 = Bt + (size_t)(n0 + r0)*Kx + c0*8;
    const __nv_bfloat16* pB1 = Bt + (size_t)(n0 + r1)*Kx + c1*8;

    uint32_t sA = (uint32_t)__cvta_generic_to_shared(As);
    uint32_t sB = (uint32_t)__cvta_generic_to_shared(Bs);
    uint32_t dA0 = sA + (r0*AST + c0*4)*4;
    uint32_t dA1 = sA + (r1*AST + c1*4)*4;
    uint32_t dB0 = sB + (r0*AST + c0*4)*4;
    uint32_t dB1 = sB + (r1*AST + c1*4)*4;

    // ldmatrix per-lane row/byte components
    // A frag: matrices (mlo,klo)(mhi,klo)(mlo,khi)(mhi,khi)
    int aRow = ((lane >> 3) & 1)*8 + r8;      // + wm*64 + mt*16
    int aKb  = ((lane >> 4) & 1)*16;
    // B frag (pair p covers nt=2p,2p+1): (n lo,klo)(n lo,khi)(n hi,klo)(n hi,khi)
    int bRow = ((lane >> 4) & 1)*8 + r8;      // + wn*32 + p*16
    int bKb  = ((lane >> 3) & 1)*16;

    float acc[4][4][4];
    #pragma unroll
    for (int i = 0; i < 4; i++)
        #pragma unroll
        for (int j = 0; j < 4; j++)
            #pragma unroll
            for (int r = 0; r < 4; r++) acc[i][j][r] = 0.f;

    const int NC = Kx >> 5;

    asm volatile("cp.async.cg.shared.global [%0], [%1], 16;\n" :: "r"(dA0), "l"(pA0));
    asm volatile("cp.async.cg.shared.global [%0], [%1], 16;\n" :: "r"(dA1), "l"(pA1));
    asm volatile("cp.async.cg.shared.global [%0], [%1], 16;\n" :: "r"(dB0), "l"(pB0));
    asm volatile("cp.async.cg.shared.global [%0], [%1], 16;\n" :: "r"(dB1), "l"(pB1));
    asm volatile("cp.async.commit_group;\n");

    for (int c = 0; c < NC; c++) {
        const int s = c & 1;
        const int sn = s ^ 1;
        asm volatile("cp.async.wait_group 0;\n");
        __syncthreads();

        if (c + 1 < NC) {
            int ko = (c + 1) << 5;
            uint32_t off = sn*STG*4;
            asm volatile("cp.async.cg.shared.global [%0], [%1], 16;\n"
                         :: "r"(dA0 + off), "l"(pA0 + ko));
            asm volatile("cp.async.cg.shared.global [%0], [%1], 16;\n"
                         :: "r"(dA1 + off), "l"(pA1 + ko));
            asm volatile("cp.async.cg.shared.global [%0], [%1], 16;\n"
                         :: "r"(dB0 + off), "l"(pB0 + ko));
            asm volatile("cp.async.cg.shared.global [%0], [%1], 16;\n"
                         :: "r"(dB1 + off), "l"(pB1 + ko));
            asm volatile("cp.async.commit_group;\n");
        }

        uint32_t baseA = sA + s*STG*4;
        uint32_t baseB = sB + s*STG*4;

        #pragma unroll
        for (int ss = 0; ss < 2; ss++) {
            uint32_t a[4][4], b[4][2];
            #pragma unroll
            for (int mt = 0; mt < 4; mt++) {
                uint32_t addr = baseA + ((wm*64 + mt*16 + aRow)*AST + ss*8)*4 + aKb;
                LDSM4(a[mt][0], a[mt][1], a[mt][2], a[mt][3], addr);
            }
            #pragma unroll
            for (int p = 0; p < 2; p++) {
                uint32_t addr = baseB + ((wn*32 + p*16 + bRow)*AST + ss*8)*4 + bKb;
                LDSM4(b[2*p][0], b[2*p][1], b[2*p+1][0], b[2*p+1][1], addr);
            }
            #pragma unroll
            for (int mt = 0; mt < 4; mt++)
                #pragma unroll
                for (int nt = 0; nt < 4; nt++) {
                    asm volatile(
                        "mma.sync.aligned.m16n8k16.row.col.f32.bf16.bf16.f32 "
                        "{%0,%1,%2,%3}, {%4,%5,%6,%7}, {%8,%9}, {%0,%1,%2,%3};"
                        : "+f"(acc[mt][nt][0]), "+f"(acc[mt][nt][1]),
                          "+f"(acc[mt][nt][2]), "+f"(acc[mt][nt][3])
                        : "r"(a[mt][0]), "r"(a[mt][1]), "r"(a[mt][2]), "r"(a[mt][3]),
                          "r"(b[nt][0]), "r"(b[nt][1]));
                }
        }
    }

    if (mode == 0) {
        float* C = (float*)Cv;
        #pragma unroll
        for (int mt = 0; mt < 4; mt++) {
            int row0 = m0 + wm*64 + mt*16 + g;
            #pragma unroll
            for (int nt = 0; nt < 4; nt++) {
                int col = n0 + wn*32 + nt*8 + 2*t;
                float b0 = bias[col], b1 = bias[col+1];
                C[(size_t)row0*N + col]         = acc[mt][nt][0] + b0;
                C[(size_t)row0*N + col + 1]     = acc[mt][nt][1] + b1;
                C[(size_t)(row0+8)*N + col]     = acc[mt][nt][2] + b0;
                C[(size_t)(row0+8)*N + col + 1] = acc[mt][nt][3] + b1;
            }
        }
    } else {
        __nv_bfloat16* D = (__nv_bfloat16*)Cv;
        float sc = (mode == 1) ? 0.125f : 1.0f;
        #pragma unroll
        for (int mt = 0; mt < 4; mt++) {
            int row0 = m0 + wm*64 + mt*16 + g;
            #pragma unroll
            for (int nt = 0; nt < 4; nt++) {
                int col = n0 + wn*32 + nt*8 + 2*t;
                float b0 = bias[col], b1 = bias[col+1];
                #pragma unroll
                for (int half = 0; half < 2; half++) {
                    int row = row0 + half*8;
                    int bb = row >> 11, s = row & 2047;
                    int hh = col >> 6, hd = col & 63;
                    size_t base = ((size_t)(bb*HH + hh)*SQ + s)*192;
                    float v0 = (acc[mt][nt][half*2]     + b0) * sc;
                    float v1 = (acc[mt][nt][half*2 + 1] + b1) * sc;
                    __nv_bfloat16 h0 = __float2bfloat16(v0);
                    __nv_bfloat16 l0 = __float2bfloat16(v0 - __bfloat162float(h0));
                    __nv_bfloat16 h1 = __float2bfloat16(v1);
                    __nv_bfloat16 l1 = __float2bfloat16(v1 - __bfloat162float(h1));
                    __nv_bfloat162 hp = __nv_bfloat162(h0, h1);
                    __nv_bfloat162 lp = __nv_bfloat162(l0, l1);
                    if (mode == 1) {   // Q: [h|h|l]
                        *(__nv_bfloat162*)&D[base + hd]       = hp;
                        *(__nv_bfloat162*)&D[base + 64 + hd]  = hp;
                        *(__nv_bfloat162*)&D[base + 128 + hd] = lp;
                    } else {           // K: [h|l|h]
                        *(__nv_bfloat162*)&D[base + hd]       = hp;
                        *(__nv_bfloat162*)&D[base + 64 + hd]  = lp;
                        *(__nv_bfloat162*)&D[base + 128 + hd] = hp;
                    }
                }
            }
        }
    }
}

// ---------------------------------------------------------------------------
// HMMA flash attention v3: R14 structure + ldmatrix fragment loads +
// packed bf16x2 P/epilogue stores. Layouts unchanged (QST=100, VST=52).
// ---------------------------------------------------------------------------
#define QST 100
#define VST 52

__global__ __launch_bounds__(256) void attn_mma()
{
    __shared__ __align__(16) uint32_t U[6656];     // Q3s / V3s(3328)+P3s(3328)
    __shared__ __align__(16) uint32_t K3s[32*QST];
    __shared__ float mrow[64], lrow[64];
    __shared__ float pmax[64][2], psum[64][2];

    int tid = threadIdx.x, lane = tid & 31, w = tid >> 5;
    int g = lane >> 2, t = lane & 3;
    int r8 = lane & 7;
    int q0 = blockIdx.x * 64;
    int bh = blockIdx.z * HH + blockIdx.y;

    int wm = w >> 1, wn = w & 1;
    int r0 = wm*16 + g, r1 = r0 + 8;

    // ldmatrix lane components
    int aRow = ((lane >> 3) & 1)*8 + r8;   // A-frag pattern
    int aKb  = ((lane >> 4) & 1)*16;
    int bRow = ((lane >> 4) & 1)*8 + r8;   // B-frag pattern
    int bKb  = ((lane >> 3) & 1)*16;

    // --- Q3 tile -> persistent A-fragments ---
    const __nv_bfloat16* Qg = g_q3 + ((size_t)bh*SQ + q0)*192;
    #pragma unroll
    for (int i = 0; i < 6; i++) {
        int idx = tid + i*256;
        int r = idx / 24, c = idx % 24;
        *(uint4*)&U[r*QST + c*4] = *(const uint4*)(Qg + (size_t)r*192 + c*8);
    }
    if (tid < 64) { mrow[tid] = -INFINITY; lrow[tid] = 0.f; }
    __syncthreads();

    uint32_t sU = (uint32_t)__cvta_generic_to_shared(U);
    uint32_t sK = (uint32_t)__cvta_generic_to_shared(K3s);

    uint32_t qa[12][4];
    #pragma unroll
    for (int ks = 0; ks < 12; ks++) {
        uint32_t addr = sU + ((wm*16 + aRow)*QST + ks*8)*4 + aKb;
        LDSM4(qa[ks][0], qa[ks][1], qa[ks][2], qa[ks][3], addr);
    }
    __syncthreads();

    uint32_t* V3s = U;
    uint32_t* P3s = U + 3328;
    __nv_bfloat16* P3h = (__nv_bfloat16*)P3s;
    uint32_t sV = sU;
    uint32_t sP = sU + 3328*4;

    float o[4][4] = {};

    const __nv_bfloat16* Kg = g_k3 + (size_t)bh*SQ*192;
    const __nv_bfloat16* Vg = g_v3t + (size_t)bh*HD*3*SQ;

    int kr[3], kc[3];
    #pragma unroll
    for (int i = 0; i < 3; i++) {
        int idx = tid + i*256;
        kr[i] = idx / 24;
        kc[i] = idx % 24;
    }
    int vr[3], vblk[3], vc[3];
    #pragma unroll
    for (int i = 0; i < 3; i++) {
        int idx = tid + i*256;
        vr[i] = idx / 12;
        int sub = idx % 12;
        vblk[i] = sub >> 2;
        vc[i] = sub & 3;
    }

    #pragma unroll
    for (int i = 0; i < 3; i++)
        asm volatile("cp.async.cg.shared.global [%0], [%1], 16;\n"
                     :: "r"(sK + (kr[i]*QST + kc[i]*4)*4),
                        "l"(Kg + (size_t)kr[i]*192 + kc[i]*8));
    asm volatile("cp.async.commit_group;\n");

    for (int k0 = 0; k0 < SQ; k0 += 32) {
        asm volatile("cp.async.wait_group 0;\n");
        __syncthreads();

        uint4 vreg[3];
        #pragma unroll
        for (int i = 0; i < 3; i++)
            vreg[i] = *(const uint4*)(Vg + (size_t)vr[i]*3*SQ + vblk[i]*SQ + k0 + vc[i]*8);

        // --- S = Q3 @ K3^T ---
        float sc[2][4];
        #pragma unroll
        for (int nt = 0; nt < 2; nt++)
            #pragma unroll
            for (int r = 0; r < 4; r++) sc[nt][r] = 0.f;
        #pragma unroll
        for (int ks = 0; ks < 12; ks++) {
            uint32_t bfr[2][2];
            uint32_t addr = sK + ((wn*16 + bRow)*QST + ks*8)*4 + bKb;
            LDSM4(bfr[0][0], bfr[0][1], bfr[1][0], bfr[1][1], addr);
            #pragma unroll
            for (int nt = 0; nt < 2; nt++) {
                asm volatile(
                    "mma.sync.aligned.m16n8k16.row.col.f32.bf16.bf16.f32 "
                    "{%0,%1,%2,%3}, {%4,%5,%6,%7}, {%8,%9}, {%0,%1,%2,%3};"
                    : "+f"(sc[nt][0]), "+f"(sc[nt][1]), "+f"(sc[nt][2]), "+f"(sc[nt][3])
                    : "r"(qa[ks][0]), "r"(qa[ks][1]), "r"(qa[ks][2]), "r"(qa[ks][3]),
                      "r"(bfr[nt][0]), "r"(bfr[nt][1]));
            }
        }

        #pragma unroll
        for (int i = 0; i < 3; i++)
            *(uint4*)&V3s[vr[i]*VST + vblk[i]*16 + vc[i]*4] = vreg[i];

        float mx0 = fmaxf(fmaxf(sc[0][0], sc[0][1]), fmaxf(sc[1][0], sc[1][1]));
        float mx1 = fmaxf(fmaxf(sc[0][2], sc[0][3]), fmaxf(sc[1][2], sc[1][3]));
        mx0 = fmaxf(mx0, __shfl_xor_sync(0xFFFFFFFFu, mx0, 1));
        mx0 = fmaxf(mx0, __shfl_xor_sync(0xFFFFFFFFu, mx0, 2));
        mx1 = fmaxf(mx1, __shfl_xor_sync(0xFFFFFFFFu, mx1, 1));
        mx1 = fmaxf(mx1, __shfl_xor_sync(0xFFFFFFFFu, mx1, 2));
        if (t == 0) { pmax[r0][wn] = mx0; pmax[r1][wn] = mx1; }
        __syncthreads();   // sync_A

        if (k0 + 32 < SQ) {
            #pragma unroll
            for (int i = 0; i < 3; i++)
                asm volatile("cp.async.cg.shared.global [%0], [%1], 16;\n"
                             :: "r"(sK + (kr[i]*QST + kc[i]*4)*4),
                                "l"(Kg + (size_t)(k0 + 32 + kr[i])*192 + kc[i]*8));
            asm volatile("cp.async.commit_group;\n");
        }

        float mold0 = mrow[r0], mold1 = mrow[r1];
        float lold0 = lrow[r0], lold1 = lrow[r1];
        float M0 = fmaxf(fmaxf(pmax[r0][0], pmax[r0][1]), mold0);
        float M1 = fmaxf(fmaxf(pmax[r1][0], pmax[r1][1]), mold1);
        float al0 = __expf(mold0 - M0);
        float al1 = __expf(mold1 - M1);
        float s0 = 0.f, s1 = 0.f;
        #pragma unroll
        for (int nt = 0; nt < 2; nt++) {
            float p0 = __expf(sc[nt][0] - M0);
            float p1 = __expf(sc[nt][1] - M0);
            float p2 = __expf(sc[nt][2] - M1);
            float p3 = __expf(sc[nt][3] - M1);
            s0 += p0 + p1; s1 += p2 + p3;
            int c = wn*16 + nt*8 + 2*t;
            __nv_bfloat16 h0 = __float2bfloat16(p0);
            __nv_bfloat16 l0 = __float2bfloat16(p0 - __bfloat162float(h0));
            __nv_bfloat16 h1 = __float2bfloat16(p1);
            __nv_bfloat16 l1 = __float2bfloat16(p1 - __bfloat162float(h1));
            __nv_bfloat16 h2 = __float2bfloat16(p2);
            __nv_bfloat16 l2 = __float2bfloat16(p2 - __bfloat162float(h2));
            __nv_bfloat16 h3 = __float2bfloat16(p3);
            __nv_bfloat16 l3 = __float2bfloat16(p3 - __bfloat162float(h3));
            __nv_bfloat162 hp01 = __nv_bfloat162(h0, h1);
            __nv_bfloat162 lp01 = __nv_bfloat162(l0, l1);
            __nv_bfloat162 hp23 = __nv_bfloat162(h2, h3);
            __nv_bfloat162 lp23 = __nv_bfloat162(l2, l3);
            *(__nv_bfloat162*)&P3h[r0*104 + c]      = hp01;
            *(__nv_bfloat162*)&P3h[r0*104 + 32 + c] = hp01;
            *(__nv_bfloat162*)&P3h[r0*104 + 64 + c] = lp01;
            *(__nv_bfloat162*)&P3h[r1*104 + c]      = hp23;
            *(__nv_bfloat162*)&P3h[r1*104 + 32 + c] = hp23;
            *(__nv_bfloat162*)&P3h[r1*104 + 64 + c] = lp23;
        }
        s0 += __shfl_xor_sync(0xFFFFFFFFu, s0, 1);
        s0 += __shfl_xor_sync(0xFFFFFFFFu, s0, 2);
        s1 += __shfl_xor_sync(0xFFFFFFFFu, s1, 1);
        s1 += __shfl_xor_sync(0xFFFFFFFFu, s1, 2);
        if (t == 0) { psum[r0][wn] = s0; psum[r1][wn] = s1; }
        __syncthreads();   // sync_B

        if (wn == 0 && t == 0) {
            lrow[r0] = lold0*al0 + psum[r0][0] + psum[r0][1];
            lrow[r1] = lold1*al1 + psum[r1][0] + psum[r1][1];
            mrow[r0] = M0;
            mrow[r1] = M1;
        }

        // --- O += P3 @ V3^T ---
        #pragma unroll
        for (int nt = 0; nt < 4; nt++) {
            o[nt][0] *= al0; o[nt][1] *= al0;
            o[nt][2] *= al1; o[nt][3] *= al1;
        }
        #pragma unroll
        for (int ks = 0; ks < 6; ks++) {
            uint32_t pa[4], vb[4][2];
            uint32_t pAddr = sP + ((wm*16 + aRow)*VST + ks*8)*4 + aKb;
            LDSM4(pa[0], pa[1], pa[2], pa[3], pAddr);
            #pragma unroll
            for (int p = 0; p < 2; p++) {
                uint32_t vAddr = sV + ((wn*32 + p*16 + bRow)*VST + ks*8)*4 + bKb;
                LDSM4(vb[2*p][0], vb[2*p][1], vb[2*p+1][0], vb[2*p+1][1], vAddr);
            }
            #pragma unroll
            for (int nt = 0; nt < 4; nt++) {
                asm volatile(
                    "mma.sync.aligned.m16n8k16.row.col.f32.bf16.bf16.f32 "
                    "{%0,%1,%2,%3}, {%4,%5,%6,%7}, {%8,%9}, {%0,%1,%2,%3};"
                    : "+f"(o[nt][0]), "+f"(o[nt][1]), "+f"(o[nt][2]), "+f"(o[nt][3])
                    : "r"(pa[0]), "r"(pa[1]), "r"(pa[2]), "r"(pa[3]),
                      "r"(vb[nt][0]), "r"(vb[nt][1]));
            }
        }
    }

    __syncthreads();

    // epilogue: normalize + split-write g_o3 ([h|h|l]), packed bf16x2
    int b = blockIdx.z, h = blockIdx.y;
    float i0 = 1.f / lrow[r0];
    float i1 = 1.f / lrow[r1];
    size_t b0 = (size_t)(b*SQ + q0 + r0)*K3;
    size_t b1 = (size_t)(b*SQ + q0 + r1)*K3;
    #pragma unroll
    for (int nt = 0; nt < 4; nt++) {
        int col = h*64 + wn*32 + nt*8 + 2*t;
        float v00 = o[nt][0] * i0, v01 = o[nt][1] * i0;
        float v10 = o[nt][2] * i1, v11 = o[nt][3] * i1;
        __nv_bfloat16 h00 = __float2bfloat16(v00);
        __nv_bfloat16 l00 = __float2bfloat16(v00 - __bfloat162float(h00));
        __nv_bfloat16 h01 = __float2bfloat16(v01);
        __nv_bfloat16 l01 = __float2bfloat16(v01 - __bfloat162float(h01));
        __nv_bfloat16 h10 = __float2bfloat16(v10);
        __nv_bfloat16 l10 = __float2bfloat16(v10 - __bfloat162float(h10));
        __nv_bfloat16 h11 = __float2bfloat16(v11);
        __nv_bfloat16 l11 = __float2bfloat16(v11 - __bfloat162float(h11));
        __nv_bfloat162 hp0 = __nv_bfloat162(h00, h01);
        __nv_bfloat162 lp0 = __nv_bfloat162(l00, l01);
        __nv_bfloat162 hp1 = __nv_bfloat162(h10, h11);
        __nv_bfloat162 lp1 = __nv_bfloat162(l10, l11);
        *(__nv_bfloat162*)&g_o3[b0 + col]        = hp0;
        *(__nv_bfloat162*)&g_o3[b0 + DM + col]   = hp0;
        *(__nv_bfloat162*)&g_o3[b0 + 2*DM + col] = lp0;
        *(__nv_bfloat162*)&g_o3[b1 + col]        = hp1;
        *(__nv_bfloat162*)&g_o3[b1 + DM + col]   = hp1;
        *(__nv_bfloat162*)&g_o3[b1 + 2*DM + col] = lp1;
    }
}

extern "C" void kernel_launch(void* const* d_in, const int* in_sizes, int n_in,
                              void* d_out, int out_size)
{
    const float* x  = (const float*)d_in[0];
    const float* wq = (const float*)d_in[1];
    const float* bq = (const float*)d_in[2];
    const float* wk = (const float*)d_in[3];
    const float* bk = (const float*)d_in[4];
    const float* wv = (const float*)d_in[5];
    const float* bv = (const float*)d_in[6];
    const float* wo = (const float*)d_in[7];
    const float* bo = (const float*)d_in[8];
    float* out = (float*)d_out;

    float *v;
    __nv_bfloat16 *x3, *o3, *wq3, *wk3, *wv3, *wo3, *q3, *k3;
    cudaGetSymbolAddress((void**)&v, g_v);
    cudaGetSymbolAddress((void**)&x3, g_x3);
    cudaGetSymbolAddress((void**)&o3, g_o3);
    cudaGetSymbolAddress((void**)&wq3, g_wq3);
    cudaGetSymbolAddress((void**)&wk3, g_wk3);
    cudaGetSymbolAddress((void**)&wv3, g_wv3);
    cudaGetSymbolAddress((void**)&wo3, g_wo3);
    cudaGetSymbolAddress((void**)&q3, g_q3);
    cudaGetSymbolAddress((void**)&k3, g_k3);

    int eb = (MR*DM + 255)/256;
    dim3 tb(DM/32, DM/32);
    dim3 gg(DM/128, MR/128);

    expand_a3<<<eb, 256>>>(x, x3, MR, DM);
    expand_b3t<<<tb, 256>>>(wq, wq3, DM, DM);
    expand_b3t<<<tb, 256>>>(wk, wk3, DM, DM);
    expand_b3t<<<tb, 256>>>(wv, wv3, DM, DM);
    gemm_bf16<<<gg, 256>>>(x3, wq3, bq, q3, MR, DM, K3, 1);
    gemm_bf16<<<gg, 256>>>(x3, wk3, bk, k3, MR, DM, K3, 2);
    gemm_bf16<<<gg, 256>>>(x3, wv3, bv, v,  MR, DM, K3, 0);

    expand_v3t<<<dim3(SQ/32, HD/32, BZ*HH), 256>>>(v);

    attn_mma<<<dim3(SQ/64, HH, BZ), 256>>>();

    expand_b3t<<<tb, 256>>>(wo, wo3, DM, DM);
    gemm_bf16<<<gg, 256>>>(o3, wo3, bo, out, MR, DM, K3, 0);
}

// round 16
// speedup vs baseline: 1.5185x; 1.5185x over previous
#include <cuda_runtime.h>
#include <cuda_bf16.h>
#include <cstdint>
#include <math.h>

#define BZ   2
#define SQ   2048
#define DM   1024
#define HH   16
#define HD   64
#define MR   (BZ*SQ)      // 4096 rows
#define K3   (3*DM)       // 3072 expanded-K

// ---- device-global scratch (no allocations allowed) ----
__device__ float g_v[(size_t)MR*DM];
__device__ __align__(16) __nv_bfloat16 g_x3[(size_t)MR*K3];
__device__ __align__(16) __nv_bfloat16 g_o3[(size_t)MR*K3];
__device__ __align__(16) __nv_bfloat16 g_wq3[(size_t)DM*K3];   // [N][K3]
__device__ __align__(16) __nv_bfloat16 g_wk3[(size_t)DM*K3];
__device__ __align__(16) __nv_bfloat16 g_wv3[(size_t)DM*K3];
__device__ __align__(16) __nv_bfloat16 g_wo3[(size_t)DM*K3];
__device__ __align__(16) __nv_bfloat16 g_q3[(size_t)BZ*HH*SQ*192];     // [bh][s][h|h|l]
__device__ __align__(16) __nv_bfloat16 g_k3[(size_t)BZ*HH*SQ*192];     // [bh][s][h|l|h]
__device__ __align__(16) __nv_bfloat16 g_v3t[(size_t)BZ*HH*HD*3*SQ];   // [bh][hd][Vh|Vl|Vh over s]

// ---------------------------------------------------------------------------
// Split expansions (unchanged, proven)
// ---------------------------------------------------------------------------
__global__ __launch_bounds__(256) void expand_a3(
    const float* __restrict__ src, __nv_bfloat16* __restrict__ dst, int M, int K)
{
    int idx = blockIdx.x*256 + threadIdx.x;
    if (idx >= M*K) return;
    int m = idx / K, k = idx - m*K;
    float x = src[idx];
    __nv_bfloat16 h = __float2bfloat16(x);
    __nv_bfloat16 l = __float2bfloat16(x - __bfloat162float(h));
    size_t base = (size_t)m*3*K;
    dst[base + k] = h;
    dst[base + K + k] = h;
    dst[base + 2*K + k] = l;
}

__global__ __launch_bounds__(256) void expand_b3t(
    const float* __restrict__ src, __nv_bfloat16* __restrict__ dst, int K, int N)
{
    __shared__ float t[32][33];
    int tx = threadIdx.x & 31, ty = threadIdx.x >> 5;
    int nb = blockIdx.x * 32, kb = blockIdx.y * 32;
    #pragma unroll
    for (int i = 0; i < 4; i++)
        t[ty + 8*i][tx] = src[(size_t)(kb + ty + 8*i)*N + nb + tx];
    __syncthreads();
    #pragma unroll
    for (int i = 0; i < 4; i++) {
        int n = nb + ty + 8*i;
        int k = kb + tx;
        float x = t[tx][ty + 8*i];
        __nv_bfloat16 h = __float2bfloat16(x);
        __nv_bfloat16 l = __float2bfloat16(x - __bfloat162float(h));
        size_t base = (size_t)n*3*K;
        dst[base + k]       = h;
        dst[base + K + k]   = l;
        dst[base + 2*K + k] = h;
    }
}

__global__ __launch_bounds__(256) void expand_v3t(const float* __restrict__ src)
{
    __shared__ float t[32][33];
    int tx = threadIdx.x & 31, ty = threadIdx.x >> 5;
    int s0 = blockIdx.x * 32;
    int hd0 = blockIdx.y * 32;
    int bh = blockIdx.z;
    int b = bh >> 4, h = bh & 15;
    #pragma unroll
    for (int i = 0; i < 4; i++)
        t[ty + 8*i][tx] = src[(size_t)(b*SQ + s0 + ty + 8*i)*DM + h*64 + hd0 + tx];
    __syncthreads();
    #pragma unroll
    for (int i = 0; i < 4; i++) {
        int hd = hd0 + ty + 8*i;
        float x = t[tx][ty + 8*i];
        __nv_bfloat16 hh = __float2bfloat16(x);
        __nv_bfloat16 ll = __float2bfloat16(x - __bfloat162float(hh));
        size_t base = ((size_t)bh*HD + hd)*3*SQ;
        g_v3t[base + s0 + tx]        = hh;
        g_v3t[base + SQ + s0 + tx]   = ll;
        g_v3t[base + 2*SQ + s0 + tx] = hh;
    }
}

// ---------------------------------------------------------------------------
// bf16 HMMA GEMM v5 (R14-exact scalar-LDS feeding, cp.async double-buffer).
// mode 0: fp32 out. mode 1: split [h|h|l] -> g_q3 (x0.125). mode 2: [h|l|h] -> g_k3.
// Packed bf16x2 split-epilogue stores (store-side only change vs R14).
// ---------------------------------------------------------------------------
#define AST 20
#define STG (128*AST)

__global__ __launch_bounds__(256) void gemm_bf16(
    const __nv_bfloat16* __restrict__ A, const __nv_bfloat16* __restrict__ Bt,
    const float* __restrict__ bias, void* __restrict__ Cv,
    int M, int N, int Kx, int mode)
{
    __shared__ __align__(16) uint32_t As[2*STG];
    __shared__ __align__(16) uint32_t Bs[2*STG];

    int tid = threadIdx.x;
    int lane = tid & 31;
    int w = tid >> 5;
    int wm = w >> 2;
    int wn = w & 3;
    int g = lane >> 2;
    int t = lane & 3;

    int m0 = blockIdx.y * 128;
    int n0 = blockIdx.x * 128;

    const int r0 = tid >> 2,  c0 = tid & 3;
    const int r1 = r0 + 64,   c1 = c0;

    const __nv_bfloat16* pA0 = A  + (size_t)(m0 + r0)*Kx + c0*8;
    const __nv_bfloat16* pA1 = A  + (size_t)(m0 + r1)*Kx + c1*8;
    const __nv_bfloat16* pB0 = Bt + (size_t)(n0 + r0)*Kx + c0*8;
    const __nv_bfloat16* pB1 = Bt + (size_t)(n0 + r1)*Kx + c1*8;

    uint32_t sA = (uint32_t)__cvta_generic_to_shared(As);
    uint32_t sB = (uint32_t)__cvta_generic_to_shared(Bs);
    uint32_t dA0 = sA + (r0*AST + c0*4)*4;
    uint32_t dA1 = sA + (r1*AST + c1*4)*4;
    uint32_t dB0 = sB + (r0*AST + c0*4)*4;
    uint32_t dB1 = sB + (r1*AST + c1*4)*4;

    float acc[4][4][4];
    #pragma unroll
    for (int i = 0; i < 4; i++)
        #pragma unroll
        for (int j = 0; j < 4; j++)
            #pragma unroll
            for (int r = 0; r < 4; r++) acc[i][j][r] = 0.f;

    const int NC = Kx >> 5;

    asm volatile("cp.async.cg.shared.global [%0], [%1], 16;\n" :: "r"(dA0), "l"(pA0));
    asm volatile("cp.async.cg.shared.global [%0], [%1], 16;\n" :: "r"(dA1), "l"(pA1));
    asm volatile("cp.async.cg.shared.global [%0], [%1], 16;\n" :: "r"(dB0), "l"(pB0));
    asm volatile("cp.async.cg.shared.global [%0], [%1], 16;\n" :: "r"(dB1), "l"(pB1));
    asm volatile("cp.async.commit_group;\n");

    for (int c = 0; c < NC; c++) {
        const int s = c & 1;
        const int sn = s ^ 1;
        asm volatile("cp.async.wait_group 0;\n");
        __syncthreads();

        if (c + 1 < NC) {
            int ko = (c + 1) << 5;
            uint32_t off = sn*STG*4;
            asm volatile("cp.async.cg.shared.global [%0], [%1], 16;\n"
                         :: "r"(dA0 + off), "l"(pA0 + ko));
            asm volatile("cp.async.cg.shared.global [%0], [%1], 16;\n"
                         :: "r"(dA1 + off), "l"(pA1 + ko));
            asm volatile("cp.async.cg.shared.global [%0], [%1], 16;\n"
                         :: "r"(dB0 + off), "l"(pB0 + ko));
            asm volatile("cp.async.cg.shared.global [%0], [%1], 16;\n"
                         :: "r"(dB1 + off), "l"(pB1 + ko));
            asm volatile("cp.async.commit_group;\n");
        }

        const uint32_t* Ab = As + s*STG;
        const uint32_t* Bb = Bs + s*STG;

        #pragma unroll
        for (int ss = 0; ss < 2; ss++) {
            uint32_t a[4][4], b[4][2];
            #pragma unroll
            for (int mt = 0; mt < 4; mt++) {
                int ar = (wm*64 + mt*16 + g)*AST + ss*8 + t;
                a[mt][0] = Ab[ar];
                a[mt][1] = Ab[ar + 8*AST];
                a[mt][2] = Ab[ar + 4];
                a[mt][3] = Ab[ar + 8*AST + 4];
            }
            #pragma unroll
            for (int nt = 0; nt < 4; nt++) {
                int br = (wn*32 + nt*8 + g)*AST + ss*8 + t;
                b[nt][0] = Bb[br];
                b[nt][1] = Bb[br + 4];
            }
            #pragma unroll
            for (int mt = 0; mt < 4; mt++)
                #pragma unroll
                for (int nt = 0; nt < 4; nt++) {
                    asm volatile(
                        "mma.sync.aligned.m16n8k16.row.col.f32.bf16.bf16.f32 "
                        "{%0,%1,%2,%3}, {%4,%5,%6,%7}, {%8,%9}, {%0,%1,%2,%3};"
                        : "+f"(acc[mt][nt][0]), "+f"(acc[mt][nt][1]),
                          "+f"(acc[mt][nt][2]), "+f"(acc[mt][nt][3])
                        : "r"(a[mt][0]), "r"(a[mt][1]), "r"(a[mt][2]), "r"(a[mt][3]),
                          "r"(b[nt][0]), "r"(b[nt][1]));
                }
        }
    }

    if (mode == 0) {
        float* C = (float*)Cv;
        #pragma unroll
        for (int mt = 0; mt < 4; mt++) {
            int row0 = m0 + wm*64 + mt*16 + g;
            #pragma unroll
            for (int nt = 0; nt < 4; nt++) {
                int col = n0 + wn*32 + nt*8 + 2*t;
                float b0 = bias[col], b1 = bias[col+1];
                C[(size_t)row0*N + col]         = acc[mt][nt][0] + b0;
                C[(size_t)row0*N + col + 1]     = acc[mt][nt][1] + b1;
                C[(size_t)(row0+8)*N + col]     = acc[mt][nt][2] + b0;
                C[(size_t)(row0+8)*N + col + 1] = acc[mt][nt][3] + b1;
            }
        }
    } else {
        __nv_bfloat16* D = (__nv_bfloat16*)Cv;
        float sc = (mode == 1) ? 0.125f : 1.0f;
        #pragma unroll
        for (int mt = 0; mt < 4; mt++) {
            int row0 = m0 + wm*64 + mt*16 + g;
            #pragma unroll
            for (int nt = 0; nt < 4; nt++) {
                int col = n0 + wn*32 + nt*8 + 2*t;
                float b0 = bias[col], b1 = bias[col+1];
                #pragma unroll
                for (int half = 0; half < 2; half++) {
                    int row = row0 + half*8;
                    int bb = row >> 11, s = row & 2047;
                    int hh = col >> 6, hd = col & 63;
                    size_t base = ((size_t)(bb*HH + hh)*SQ + s)*192;
                    float v0 = (acc[mt][nt][half*2]     + b0) * sc;
                    float v1 = (acc[mt][nt][half*2 + 1] + b1) * sc;
                    __nv_bfloat16 h0 = __float2bfloat16(v0);
                    __nv_bfloat16 l0 = __float2bfloat16(v0 - __bfloat162float(h0));
                    __nv_bfloat16 h1 = __float2bfloat16(v1);
                    __nv_bfloat16 l1 = __float2bfloat16(v1 - __bfloat162float(h1));
                    __nv_bfloat162 hp = __nv_bfloat162(h0, h1);
                    __nv_bfloat162 lp = __nv_bfloat162(l0, l1);
                    if (mode == 1) {   // Q: [h|h|l]
                        *(__nv_bfloat162*)&D[base + hd]       = hp;
                        *(__nv_bfloat162*)&D[base + 64 + hd]  = hp;
                        *(__nv_bfloat162*)&D[base + 128 + hd] = lp;
                    } else {           // K: [h|l|h]
                        *(__nv_bfloat162*)&D[base + hd]       = hp;
                        *(__nv_bfloat162*)&D[base + 64 + hd]  = lp;
                        *(__nv_bfloat162*)&D[base + 128 + hd] = hp;
                    }
                }
            }
        }
    }
}

// ---------------------------------------------------------------------------
// HMMA flash attention v2 (R14-exact scalar-LDS feeding): 3 syncs/chunk,
// K prefetch via cp.async, V-load hiding, register rescale factors.
// Packed bf16x2 P-tile + epilogue stores (store-side only change vs R14).
// ---------------------------------------------------------------------------
#define QST 100
#define VST 52

__global__ __launch_bounds__(256) void attn_mma()
{
    __shared__ __align__(16) uint32_t U[6656];     // Q3s / V3s(3328)+P3s(3328)
    __shared__ __align__(16) uint32_t K3s[32*QST];
    __shared__ float mrow[64], lrow[64];
    __shared__ float pmax[64][2], psum[64][2];

    int tid = threadIdx.x, lane = tid & 31, w = tid >> 5;
    int g = lane >> 2, t = lane & 3;
    int q0 = blockIdx.x * 64;
    int bh = blockIdx.z * HH + blockIdx.y;

    int wm = w >> 1, wn = w & 1;            // shared by S and PV phases
    int r0 = wm*16 + g, r1 = r0 + 8;

    // --- Q3 tile -> persistent A-fragments ---
    const __nv_bfloat16* Qg = g_q3 + ((size_t)bh*SQ + q0)*192;
    #pragma unroll
    for (int i = 0; i < 6; i++) {
        int idx = tid + i*256;
        int r = idx / 24, c = idx % 24;
        *(uint4*)&U[r*QST + c*4] = *(const uint4*)(Qg + (size_t)r*192 + c*8);
    }
    if (tid < 64) { mrow[tid] = -INFINITY; lrow[tid] = 0.f; }
    __syncthreads();

    uint32_t qa[12][4];
    #pragma unroll
    for (int ks = 0; ks < 12; ks++) {
        int ar = (wm*16 + g)*QST + ks*8 + t;
        qa[ks][0] = U[ar];
        qa[ks][1] = U[ar + 8*QST];
        qa[ks][2] = U[ar + 4];
        qa[ks][3] = U[ar + 8*QST + 4];
    }
    __syncthreads();

    uint32_t* V3s = U;
    uint32_t* P3s = U + 3328;
    __nv_bfloat16* P3h = (__nv_bfloat16*)P3s;

    float o[4][4] = {};   // [nt][0,1]=row r0 cols, [2,3]=row r1

    const __nv_bfloat16* Kg = g_k3 + (size_t)bh*SQ*192;
    const __nv_bfloat16* Vg = g_v3t + (size_t)bh*HD*3*SQ;

    uint32_t sK = (uint32_t)__cvta_generic_to_shared(K3s);
    int kr[3], kc[3];
    #pragma unroll
    for (int i = 0; i < 3; i++) {
        int idx = tid + i*256;
        kr[i] = idx / 24;
        kc[i] = idx % 24;
    }
    int vr[3], vblk[3], vc[3];
    #pragma unroll
    for (int i = 0; i < 3; i++) {
        int idx = tid + i*256;
        vr[i] = idx / 12;
        int sub = idx % 12;
        vblk[i] = sub >> 2;
        vc[i] = sub & 3;
    }

    // prologue: cp.async K(0)
    #pragma unroll
    for (int i = 0; i < 3; i++)
        asm volatile("cp.async.cg.shared.global [%0], [%1], 16;\n"
                     :: "r"(sK + (kr[i]*QST + kc[i]*4)*4),
                        "l"(Kg + (size_t)kr[i]*192 + kc[i]*8));
    asm volatile("cp.async.commit_group;\n");

    for (int k0 = 0; k0 < SQ; k0 += 32) {
        asm volatile("cp.async.wait_group 0;\n");
        __syncthreads();   // K(c) visible; V3s/P3s free

        uint4 vreg[3];
        #pragma unroll
        for (int i = 0; i < 3; i++)
            vreg[i] = *(const uint4*)(Vg + (size_t)vr[i]*3*SQ + vblk[i]*SQ + k0 + vc[i]*8);

        // --- S = Q3 @ K3^T ---
        float sc[2][4];
        #pragma unroll
        for (int nt = 0; nt < 2; nt++)
            #pragma unroll
            for (int r = 0; r < 4; r++) sc[nt][r] = 0.f;
        #pragma unroll
        for (int ks = 0; ks < 12; ks++) {
            uint32_t bfr[2][2];
            #pragma unroll
            for (int nt = 0; nt < 2; nt++) {
                int br = (wn*16 + nt*8 + g)*QST + ks*8 + t;
                bfr[nt][0] = K3s[br];
                bfr[nt][1] = K3s[br + 4];
            }
            #pragma unroll
            for (int nt = 0; nt < 2; nt++) {
                asm volatile(
                    "mma.sync.aligned.m16n8k16.row.col.f32.bf16.bf16.f32 "
                    "{%0,%1,%2,%3}, {%4,%5,%6,%7}, {%8,%9}, {%0,%1,%2,%3};"
                    : "+f"(sc[nt][0]), "+f"(sc[nt][1]), "+f"(sc[nt][2]), "+f"(sc[nt][3])
                    : "r"(qa[ks][0]), "r"(qa[ks][1]), "r"(qa[ks][2]), "r"(qa[ks][3]),
                      "r"(bfr[nt][0]), "r"(bfr[nt][1]));
            }
        }

        #pragma unroll
        for (int i = 0; i < 3; i++)
            *(uint4*)&V3s[vr[i]*VST + vblk[i]*16 + vc[i]*4] = vreg[i];

        float mx0 = fmaxf(fmaxf(sc[0][0], sc[0][1]), fmaxf(sc[1][0], sc[1][1]));
        float mx1 = fmaxf(fmaxf(sc[0][2], sc[0][3]), fmaxf(sc[1][2], sc[1][3]));
        mx0 = fmaxf(mx0, __shfl_xor_sync(0xFFFFFFFFu, mx0, 1));
        mx0 = fmaxf(mx0, __shfl_xor_sync(0xFFFFFFFFu, mx0, 2));
        mx1 = fmaxf(mx1, __shfl_xor_sync(0xFFFFFFFFu, mx1, 1));
        mx1 = fmaxf(mx1, __shfl_xor_sync(0xFFFFFFFFu, mx1, 2));
        if (t == 0) { pmax[r0][wn] = mx0; pmax[r1][wn] = mx1; }
        __syncthreads();   // sync_A

        if (k0 + 32 < SQ) {
            #pragma unroll
            for (int i = 0; i < 3; i++)
                asm volatile("cp.async.cg.shared.global [%0], [%1], 16;\n"
                             :: "r"(sK + (kr[i]*QST + kc[i]*4)*4),
                                "l"(Kg + (size_t)(k0 + 32 + kr[i])*192 + kc[i]*8));
            asm volatile("cp.async.commit_group;\n");
        }

        float mold0 = mrow[r0], mold1 = mrow[r1];
        float lold0 = lrow[r0], lold1 = lrow[r1];
        float M0 = fmaxf(fmaxf(pmax[r0][0], pmax[r0][1]), mold0);
        float M1 = fmaxf(fmaxf(pmax[r1][0], pmax[r1][1]), mold1);
        float al0 = __expf(mold0 - M0);
        float al1 = __expf(mold1 - M1);
        float s0 = 0.f, s1 = 0.f;
        #pragma unroll
        for (int nt = 0; nt < 2; nt++) {
            float p0 = __expf(sc[nt][0] - M0);
            float p1 = __expf(sc[nt][1] - M0);
            float p2 = __expf(sc[nt][2] - M1);
            float p3 = __expf(sc[nt][3] - M1);
            s0 += p0 + p1; s1 += p2 + p3;
            int c = wn*16 + nt*8 + 2*t;
            __nv_bfloat16 h0 = __float2bfloat16(p0);
            __nv_bfloat16 l0 = __float2bfloat16(p0 - __bfloat162float(h0));
            __nv_bfloat16 h1 = __float2bfloat16(p1);
            __nv_bfloat16 l1 = __float2bfloat16(p1 - __bfloat162float(h1));
            __nv_bfloat16 h2 = __float2bfloat16(p2);
            __nv_bfloat16 l2 = __float2bfloat16(p2 - __bfloat162float(h2));
            __nv_bfloat16 h3 = __float2bfloat16(p3);
            __nv_bfloat16 l3 = __float2bfloat16(p3 - __bfloat162float(h3));
            __nv_bfloat162 hp01 = __nv_bfloat162(h0, h1);
            __nv_bfloat162 lp01 = __nv_bfloat162(l0, l1);
            __nv_bfloat162 hp23 = __nv_bfloat162(h2, h3);
            __nv_bfloat162 lp23 = __nv_bfloat162(l2, l3);
            *(__nv_bfloat162*)&P3h[r0*104 + c]      = hp01;
            *(__nv_bfloat162*)&P3h[r0*104 + 32 + c] = hp01;
            *(__nv_bfloat162*)&P3h[r0*104 + 64 + c] = lp01;
            *(__nv_bfloat162*)&P3h[r1*104 + c]      = hp23;
            *(__nv_bfloat162*)&P3h[r1*104 + 32 + c] = hp23;
            *(__nv_bfloat162*)&P3h[r1*104 + 64 + c] = lp23;
        }
        s0 += __shfl_xor_sync(0xFFFFFFFFu, s0, 1);
        s0 += __shfl_xor_sync(0xFFFFFFFFu, s0, 2);
        s1 += __shfl_xor_sync(0xFFFFFFFFu, s1, 1);
        s1 += __shfl_xor_sync(0xFFFFFFFFu, s1, 2);
        if (t == 0) { psum[r0][wn] = s0; psum[r1][wn] = s1; }
        __syncthreads();   // sync_B

        if (wn == 0 && t == 0) {
            lrow[r0] = lold0*al0 + psum[r0][0] + psum[r0][1];
            lrow[r1] = lold1*al1 + psum[r1][0] + psum[r1][1];
            mrow[r0] = M0;
            mrow[r1] = M1;
        }

        // --- O += P3 @ V3^T ---
        #pragma unroll
        for (int nt = 0; nt < 4; nt++) {
            o[nt][0] *= al0; o[nt][1] *= al0;
            o[nt][2] *= al1; o[nt][3] *= al1;
        }
        #pragma unroll
        for (int ks = 0; ks < 6; ks++) {
            uint32_t pa[4], vb[4][2];
            int ar = (wm*16 + g)*VST + ks*8 + t;
            pa[0] = P3s[ar];
            pa[1] = P3s[ar + 8*VST];
            pa[2] = P3s[ar + 4];
            pa[3] = P3s[ar + 8*VST + 4];
            #pragma unroll
            for (int nt = 0; nt < 4; nt++) {
                int br = (wn*32 + nt*8 + g)*VST + ks*8 + t;
                vb[nt][0] = V3s[br];
                vb[nt][1] = V3s[br + 4];
            }
            #pragma unroll
            for (int nt = 0; nt < 4; nt++) {
                asm volatile(
                    "mma.sync.aligned.m16n8k16.row.col.f32.bf16.bf16.f32 "
                    "{%0,%1,%2,%3}, {%4,%5,%6,%7}, {%8,%9}, {%0,%1,%2,%3};"
                    : "+f"(o[nt][0]), "+f"(o[nt][1]), "+f"(o[nt][2]), "+f"(o[nt][3])
                    : "r"(pa[0]), "r"(pa[1]), "r"(pa[2]), "r"(pa[3]),
                      "r"(vb[nt][0]), "r"(vb[nt][1]));
            }
        }
    }

    __syncthreads();

    // epilogue: normalize + split-write g_o3 ([h|h|l]), packed bf16x2
    int b = blockIdx.z, h = blockIdx.y;
    float i0 = 1.f / lrow[r0];
    float i1 = 1.f / lrow[r1];
    size_t b0 = (size_t)(b*SQ + q0 + r0)*K3;
    size_t b1 = (size_t)(b*SQ + q0 + r1)*K3;
    #pragma unroll
    for (int nt = 0; nt < 4; nt++) {
        int col = h*64 + wn*32 + nt*8 + 2*t;
        float v00 = o[nt][0] * i0, v01 = o[nt][1] * i0;
        float v10 = o[nt][2] * i1, v11 = o[nt][3] * i1;
        __nv_bfloat16 h00 = __float2bfloat16(v00);
        __nv_bfloat16 l00 = __float2bfloat16(v00 - __bfloat162float(h00));
        __nv_bfloat16 h01 = __float2bfloat16(v01);
        __nv_bfloat16 l01 = __float2bfloat16(v01 - __bfloat162float(h01));
        __nv_bfloat16 h10 = __float2bfloat16(v10);
        __nv_bfloat16 l10 = __float2bfloat16(v10 - __bfloat162float(h10));
        __nv_bfloat16 h11 = __float2bfloat16(v11);
        __nv_bfloat16 l11 = __float2bfloat16(v11 - __bfloat162float(h11));
        __nv_bfloat162 hp0 = __nv_bfloat162(h00, h01);
        __nv_bfloat162 lp0 = __nv_bfloat162(l00, l01);
        __nv_bfloat162 hp1 = __nv_bfloat162(h10, h11);
        __nv_bfloat162 lp1 = __nv_bfloat162(l10, l11);
        *(__nv_bfloat162*)&g_o3[b0 + col]        = hp0;
        *(__nv_bfloat162*)&g_o3[b0 + DM + col]   = hp0;
        *(__nv_bfloat162*)&g_o3[b0 + 2*DM + col] = lp0;
        *(__nv_bfloat162*)&g_o3[b1 + col]        = hp1;
        *(__nv_bfloat162*)&g_o3[b1 + DM + col]   = hp1;
        *(__nv_bfloat162*)&g_o3[b1 + 2*DM + col] = lp1;
    }
}

extern "C" void kernel_launch(void* const* d_in, const int* in_sizes, int n_in,
                              void* d_out, int out_size)
{
    const float* x  = (const float*)d_in[0];
    const float* wq = (const float*)d_in[1];
    const float* bq = (const float*)d_in[2];
    const float* wk = (const float*)d_in[3];
    const float* bk = (const float*)d_in[4];
    const float* wv = (const float*)d_in[5];
    const float* bv = (const float*)d_in[6];
    const float* wo = (const float*)d_in[7];
    const float* bo = (const float*)d_in[8];
    float* out = (float*)d_out;

    float *v;
    __nv_bfloat16 *x3, *o3, *wq3, *wk3, *wv3, *wo3, *q3, *k3;
    cudaGetSymbolAddress((void**)&v, g_v);
    cudaGetSymbolAddress((void**)&x3, g_x3);
    cudaGetSymbolAddress((void**)&o3, g_o3);
    cudaGetSymbolAddress((void**)&wq3, g_wq3);
    cudaGetSymbolAddress((void**)&wk3, g_wk3);
    cudaGetSymbolAddress((void**)&wv3, g_wv3);
    cudaGetSymbolAddress((void**)&wo3, g_wo3);
    cudaGetSymbolAddress((void**)&q3, g_q3);
    cudaGetSymbolAddress((void**)&k3, g_k3);

    int eb = (MR*DM + 255)/256;
    dim3 tb(DM/32, DM/32);
    dim3 gg(DM/128, MR/128);

    expand_a3<<<eb, 256>>>(x, x3, MR, DM);
    expand_b3t<<<tb, 256>>>(wq, wq3, DM, DM);
    expand_b3t<<<tb, 256>>>(wk, wk3, DM, DM);
    expand_b3t<<<tb, 256>>>(wv, wv3, DM, DM);
    gemm_bf16<<<gg, 256>>>(x3, wq3, bq, q3, MR, DM, K3, 1);
    gemm_bf16<<<gg, 256>>>(x3, wk3, bk, k3, MR, DM, K3, 2);
    gemm_bf16<<<gg, 256>>>(x3, wv3, bv, v,  MR, DM, K3, 0);

    expand_v3t<<<dim3(SQ/32, HD/32, BZ*HH), 256>>>(v);

    attn_mma<<<dim3(SQ/64, HH, BZ), 256>>>();

    expand_b3t<<<tb, 256>>>(wo, wo3, DM, DM);
    gemm_bf16<<<gg, 256>>>(o3, wo3, bo, out, MR, DM, K3, 0);
}

// round 17
// speedup vs baseline: 1.6871x; 1.1111x over previous
#include <cuda_runtime.h>
#include <cuda_bf16.h>
#include <cstdint>
#include <math.h>

#define BZ   2
#define SQ   2048
#define DM   1024
#define HH   16
#define HD   64
#define MR   (BZ*SQ)      // 4096 rows
#define K3   (3*DM)       // 3072 expanded-K

// ---- device-global scratch (no allocations allowed) ----
__device__ float g_v[(size_t)MR*DM];
__device__ __align__(16) __nv_bfloat16 g_x3[(size_t)MR*K3];
__device__ __align__(16) __nv_bfloat16 g_o3[(size_t)MR*K3];
__device__ __align__(16) __nv_bfloat16 g_wq3[(size_t)DM*K3];   // [N][K3]
__device__ __align__(16) __nv_bfloat16 g_wk3[(size_t)DM*K3];
__device__ __align__(16) __nv_bfloat16 g_wv3[(size_t)DM*K3];
__device__ __align__(16) __nv_bfloat16 g_wo3[(size_t)DM*K3];
// attention split operands, DE-DUPLICATED [h|l]:
__device__ __align__(16) __nv_bfloat16 g_q3[(size_t)BZ*HH*SQ*128];     // [bh][s][Qh|Ql]
__device__ __align__(16) __nv_bfloat16 g_k3[(size_t)BZ*HH*SQ*128];     // [bh][s][Kh|Kl]
__device__ __align__(16) __nv_bfloat16 g_v3t[(size_t)BZ*HH*HD*2*SQ];   // [bh][hd][Vh|Vl over s]

// ---------------------------------------------------------------------------
// Split expansions (GEMM-side unchanged, proven)
// ---------------------------------------------------------------------------
__global__ __launch_bounds__(256) void expand_a3(
    const float* __restrict__ src, __nv_bfloat16* __restrict__ dst, int M, int K)
{
    int idx = blockIdx.x*256 + threadIdx.x;
    if (idx >= M*K) return;
    int m = idx / K, k = idx - m*K;
    float x = src[idx];
    __nv_bfloat16 h = __float2bfloat16(x);
    __nv_bfloat16 l = __float2bfloat16(x - __bfloat162float(h));
    size_t base = (size_t)m*3*K;
    dst[base + k] = h;
    dst[base + K + k] = h;
    dst[base + 2*K + k] = l;
}

__global__ __launch_bounds__(256) void expand_b3t(
    const float* __restrict__ src, __nv_bfloat16* __restrict__ dst, int K, int N)
{
    __shared__ float t[32][33];
    int tx = threadIdx.x & 31, ty = threadIdx.x >> 5;
    int nb = blockIdx.x * 32, kb = blockIdx.y * 32;
    #pragma unroll
    for (int i = 0; i < 4; i++)
        t[ty + 8*i][tx] = src[(size_t)(kb + ty + 8*i)*N + nb + tx];
    __syncthreads();
    #pragma unroll
    for (int i = 0; i < 4; i++) {
        int n = nb + ty + 8*i;
        int k = kb + tx;
        float x = t[tx][ty + 8*i];
        __nv_bfloat16 h = __float2bfloat16(x);
        __nv_bfloat16 l = __float2bfloat16(x - __bfloat162float(h));
        size_t base = (size_t)n*3*K;
        dst[base + k]       = h;
        dst[base + K + k]   = l;
        dst[base + 2*K + k] = h;
    }
}

// V transpose-expand: per (b,h): dst [hd][2*SQ] = [Vh | Vl] over s
__global__ __launch_bounds__(256) void expand_v3t(const float* __restrict__ src)
{
    __shared__ float t[32][33];
    int tx = threadIdx.x & 31, ty = threadIdx.x >> 5;
    int s0 = blockIdx.x * 32;
    int hd0 = blockIdx.y * 32;
    int bh = blockIdx.z;
    int b = bh >> 4, h = bh & 15;
    #pragma unroll
    for (int i = 0; i < 4; i++)
        t[ty + 8*i][tx] = src[(size_t)(b*SQ + s0 + ty + 8*i)*DM + h*64 + hd0 + tx];
    __syncthreads();
    #pragma unroll
    for (int i = 0; i < 4; i++) {
        int hd = hd0 + ty + 8*i;
        float x = t[tx][ty + 8*i];
        __nv_bfloat16 hh = __float2bfloat16(x);
        __nv_bfloat16 ll = __float2bfloat16(x - __bfloat162float(hh));
        size_t base = ((size_t)bh*HD + hd)*2*SQ;
        g_v3t[base + s0 + tx]      = hh;
        g_v3t[base + SQ + s0 + tx] = ll;
    }
}

// ---------------------------------------------------------------------------
// bf16 HMMA GEMM v5 (R16-exact core): cp.async double-buffer, scalar-LDS.
// mode 0: fp32 out. mode 1: split [h|l] -> g_q3 (x0.125). mode 2: [h|l] -> g_k3.
// ---------------------------------------------------------------------------
#define AST 20
#define STG (128*AST)

__global__ __launch_bounds__(256) void gemm_bf16(
    const __nv_bfloat16* __restrict__ A, const __nv_bfloat16* __restrict__ Bt,
    const float* __restrict__ bias, void* __restrict__ Cv,
    int M, int N, int Kx, int mode)
{
    __shared__ __align__(16) uint32_t As[2*STG];
    __shared__ __align__(16) uint32_t Bs[2*STG];

    int tid = threadIdx.x;
    int lane = tid & 31;
    int w = tid >> 5;
    int wm = w >> 2;
    int wn = w & 3;
    int g = lane >> 2;
    int t = lane & 3;

    int m0 = blockIdx.y * 128;
    int n0 = blockIdx.x * 128;

    const int r0 = tid >> 2,  c0 = tid & 3;
    const int r1 = r0 + 64,   c1 = c0;

    const __nv_bfloat16* pA0 = A  + (size_t)(m0 + r0)*Kx + c0*8;
    const __nv_bfloat16* pA1 = A  + (size_t)(m0 + r1)*Kx + c1*8;
    const __nv_bfloat16* pB0 = Bt + (size_t)(n0 + r0)*Kx + c0*8;
    const __nv_bfloat16* pB1 = Bt + (size_t)(n0 + r1)*Kx + c1*8;

    uint32_t sA = (uint32_t)__cvta_generic_to_shared(As);
    uint32_t sB = (uint32_t)__cvta_generic_to_shared(Bs);
    uint32_t dA0 = sA + (r0*AST + c0*4)*4;
    uint32_t dA1 = sA + (r1*AST + c1*4)*4;
    uint32_t dB0 = sB + (r0*AST + c0*4)*4;
    uint32_t dB1 = sB + (r1*AST + c1*4)*4;

    float acc[4][4][4];
    #pragma unroll
    for (int i = 0; i < 4; i++)
        #pragma unroll
        for (int j = 0; j < 4; j++)
            #pragma unroll
            for (int r = 0; r < 4; r++) acc[i][j][r] = 0.f;

    const int NC = Kx >> 5;

    asm volatile("cp.async.cg.shared.global [%0], [%1], 16;\n" :: "r"(dA0), "l"(pA0));
    asm volatile("cp.async.cg.shared.global [%0], [%1], 16;\n" :: "r"(dA1), "l"(pA1));
    asm volatile("cp.async.cg.shared.global [%0], [%1], 16;\n" :: "r"(dB0), "l"(pB0));
    asm volatile("cp.async.cg.shared.global [%0], [%1], 16;\n" :: "r"(dB1), "l"(pB1));
    asm volatile("cp.async.commit_group;\n");

    for (int c = 0; c < NC; c++) {
        const int s = c & 1;
        const int sn = s ^ 1;
        asm volatile("cp.async.wait_group 0;\n");
        __syncthreads();

        if (c + 1 < NC) {
            int ko = (c + 1) << 5;
            uint32_t off = sn*STG*4;
            asm volatile("cp.async.cg.shared.global [%0], [%1], 16;\n"
                         :: "r"(dA0 + off), "l"(pA0 + ko));
            asm volatile("cp.async.cg.shared.global [%0], [%1], 16;\n"
                         :: "r"(dA1 + off), "l"(pA1 + ko));
            asm volatile("cp.async.cg.shared.global [%0], [%1], 16;\n"
                         :: "r"(dB0 + off), "l"(pB0 + ko));
            asm volatile("cp.async.cg.shared.global [%0], [%1], 16;\n"
                         :: "r"(dB1 + off), "l"(pB1 + ko));
            asm volatile("cp.async.commit_group;\n");
        }

        const uint32_t* Ab = As + s*STG;
        const uint32_t* Bb = Bs + s*STG;

        #pragma unroll
        for (int ss = 0; ss < 2; ss++) {
            uint32_t a[4][4], b[4][2];
            #pragma unroll
            for (int mt = 0; mt < 4; mt++) {
                int ar = (wm*64 + mt*16 + g)*AST + ss*8 + t;
                a[mt][0] = Ab[ar];
                a[mt][1] = Ab[ar + 8*AST];
                a[mt][2] = Ab[ar + 4];
                a[mt][3] = Ab[ar + 8*AST + 4];
            }
            #pragma unroll
            for (int nt = 0; nt < 4; nt++) {
                int br = (wn*32 + nt*8 + g)*AST + ss*8 + t;
                b[nt][0] = Bb[br];
                b[nt][1] = Bb[br + 4];
            }
            #pragma unroll
            for (int mt = 0; mt < 4; mt++)
                #pragma unroll
                for (int nt = 0; nt < 4; nt++) {
                    asm volatile(
                        "mma.sync.aligned.m16n8k16.row.col.f32.bf16.bf16.f32 "
                        "{%0,%1,%2,%3}, {%4,%5,%6,%7}, {%8,%9}, {%0,%1,%2,%3};"
                        : "+f"(acc[mt][nt][0]), "+f"(acc[mt][nt][1]),
                          "+f"(acc[mt][nt][2]), "+f"(acc[mt][nt][3])
                        : "r"(a[mt][0]), "r"(a[mt][1]), "r"(a[mt][2]), "r"(a[mt][3]),
                          "r"(b[nt][0]), "r"(b[nt][1]));
                }
        }
    }

    if (mode == 0) {
        float* C = (float*)Cv;
        #pragma unroll
        for (int mt = 0; mt < 4; mt++) {
            int row0 = m0 + wm*64 + mt*16 + g;
            #pragma unroll
            for (int nt = 0; nt < 4; nt++) {
                int col = n0 + wn*32 + nt*8 + 2*t;
                float b0 = bias[col], b1 = bias[col+1];
                C[(size_t)row0*N + col]         = acc[mt][nt][0] + b0;
                C[(size_t)row0*N + col + 1]     = acc[mt][nt][1] + b1;
                C[(size_t)(row0+8)*N + col]     = acc[mt][nt][2] + b0;
                C[(size_t)(row0+8)*N + col + 1] = acc[mt][nt][3] + b1;
            }
        }
    } else {
        // split-write [h|l] into g_q3 / g_k3 layout [bh][s][128]
        __nv_bfloat16* D = (__nv_bfloat16*)Cv;
        float sc = (mode == 1) ? 0.125f : 1.0f;
        #pragma unroll
        for (int mt = 0; mt < 4; mt++) {
            int row0 = m0 + wm*64 + mt*16 + g;
            #pragma unroll
            for (int nt = 0; nt < 4; nt++) {
                int col = n0 + wn*32 + nt*8 + 2*t;
                float b0 = bias[col], b1 = bias[col+1];
                #pragma unroll
                for (int half = 0; half < 2; half++) {
                    int row = row0 + half*8;
                    int bb = row >> 11, s = row & 2047;
                    int hh = col >> 6, hd = col & 63;
                    size_t base = ((size_t)(bb*HH + hh)*SQ + s)*128;
                    float v0 = (acc[mt][nt][half*2]     + b0) * sc;
                    float v1 = (acc[mt][nt][half*2 + 1] + b1) * sc;
                    __nv_bfloat16 h0 = __float2bfloat16(v0);
                    __nv_bfloat16 l0 = __float2bfloat16(v0 - __bfloat162float(h0));
                    __nv_bfloat16 h1 = __float2bfloat16(v1);
                    __nv_bfloat16 l1 = __float2bfloat16(v1 - __bfloat162float(h1));
                    *(__nv_bfloat162*)&D[base + hd]      = __nv_bfloat162(h0, h1);
                    *(__nv_bfloat162*)&D[base + 64 + hd] = __nv_bfloat162(l0, l1);
                }
            }
        }
    }
}

// ---------------------------------------------------------------------------
// HMMA flash attention v4: de-duplicated [h|l] operands, explicit term
// pairing. S: 12 mma-steps (a {0-3,0-3,4-7} x b {0-3,4-7,0-3}); PV: 6 steps
// (pa {0,1,0,1,2,3} x vb {0,1,2,3,0,1}). Structure otherwise R16-exact.
// ---------------------------------------------------------------------------
#define QST 68   // u32 stride: 128 bf16 rows (Q staging, K tile)
#define VST 36   // u32 stride: 64 bf16 rows (V, P tiles)

__global__ __launch_bounds__(256) void attn_mma()
{
    __shared__ __align__(16) uint32_t U[4608];       // Qstage(4352) / V3s(2304)+P3s(2304)
    __shared__ __align__(16) uint32_t K3s[32*QST];   // 8.7 KB
    __shared__ float mrow[64], lrow[64];
    __shared__ float pmax[64][2], psum[64][2];

    int tid = threadIdx.x, lane = tid & 31, w = tid >> 5;
    int g = lane >> 2, t = lane & 3;
    int q0 = blockIdx.x * 64;
    int bh = blockIdx.z * HH + blockIdx.y;

    int wm = w >> 1, wn = w & 1;
    int r0 = wm*16 + g, r1 = r0 + 8;

    // --- Q staging (64 x 128 bf16) -> persistent A-fragments (8 ksteps) ---
    const __nv_bfloat16* Qg = g_q3 + ((size_t)bh*SQ + q0)*128;
    #pragma unroll
    for (int i = 0; i < 4; i++) {
        int idx = tid + i*256;
        int r = idx >> 4, c = idx & 15;
        *(uint4*)&U[r*QST + c*4] = *(const uint4*)(Qg + (size_t)r*128 + c*8);
    }
    if (tid < 64) { mrow[tid] = -INFINITY; lrow[tid] = 0.f; }
    __syncthreads();

    uint32_t qa[8][4];
    #pragma unroll
    for (int ks = 0; ks < 8; ks++) {
        int ar = (wm*16 + g)*QST + ks*8 + t;
        qa[ks][0] = U[ar];
        qa[ks][1] = U[ar + 8*QST];
        qa[ks][2] = U[ar + 4];
        qa[ks][3] = U[ar + 8*QST + 4];
    }
    __syncthreads();

    uint32_t* V3s = U;          // [64 hd][VST]  (Vh|Vl)
    uint32_t* P3s = U + 2304;   // [64 q][VST]   (Ph|Pl)
    __nv_bfloat16* P3h = (__nv_bfloat16*)P3s;

    float o[4][4] = {};

    const __nv_bfloat16* Kg = g_k3 + (size_t)bh*SQ*128;
    const __nv_bfloat16* Vg = g_v3t + (size_t)bh*HD*2*SQ;

    uint32_t sK = (uint32_t)__cvta_generic_to_shared(K3s);
    // K tile: 32 rows x 16 uint4 -> 2 per thread
    int kr[2], kc[2];
    #pragma unroll
    for (int i = 0; i < 2; i++) {
        int idx = tid + i*256;
        kr[i] = idx >> 4;
        kc[i] = idx & 15;
    }
    // V tile: 64 rows x 8 uint4 -> 2 per thread
    int vr[2], vblk[2], vc[2];
    #pragma unroll
    for (int i = 0; i < 2; i++) {
        int idx = tid + i*256;
        vr[i] = idx >> 3;
        int sub = idx & 7;
        vblk[i] = sub >> 2;
        vc[i] = sub & 3;
    }

    // prologue: cp.async K(0)
    #pragma unroll
    for (int i = 0; i < 2; i++)
        asm volatile("cp.async.cg.shared.global [%0], [%1], 16;\n"
                     :: "r"(sK + (kr[i]*QST + kc[i]*4)*4),
                        "l"(Kg + (size_t)kr[i]*128 + kc[i]*8));
    asm volatile("cp.async.commit_group;\n");

    for (int k0 = 0; k0 < SQ; k0 += 32) {
        asm volatile("cp.async.wait_group 0;\n");
        __syncthreads();   // K(c) visible; V3s/P3s free

        uint4 vreg[2];
        #pragma unroll
        for (int i = 0; i < 2; i++)
            vreg[i] = *(const uint4*)(Vg + (size_t)vr[i]*2*SQ + vblk[i]*SQ + k0 + vc[i]*8);

        // --- S: Qh.Kh + Qh.Kl + Ql.Kh ---
        float sc[2][4];
        #pragma unroll
        for (int nt = 0; nt < 2; nt++)
            #pragma unroll
            for (int r = 0; r < 4; r++) sc[nt][r] = 0.f;

        const int aI[12] = {0,1,2,3, 0,1,2,3, 4,5,6,7};
        const int bI[12] = {0,1,2,3, 4,5,6,7, 0,1,2,3};
        #pragma unroll
        for (int it = 0; it < 12; it++) {
            int ak = aI[it], bk = bI[it];
            uint32_t bfr[2][2];
            #pragma unroll
            for (int nt = 0; nt < 2; nt++) {
                int br = (wn*16 + nt*8 + g)*QST + bk*8 + t;
                bfr[nt][0] = K3s[br];
                bfr[nt][1] = K3s[br + 4];
            }
            #pragma unroll
            for (int nt = 0; nt < 2; nt++) {
                asm volatile(
                    "mma.sync.aligned.m16n8k16.row.col.f32.bf16.bf16.f32 "
                    "{%0,%1,%2,%3}, {%4,%5,%6,%7}, {%8,%9}, {%0,%1,%2,%3};"
                    : "+f"(sc[nt][0]), "+f"(sc[nt][1]), "+f"(sc[nt][2]), "+f"(sc[nt][3])
                    : "r"(qa[ak][0]), "r"(qa[ak][1]), "r"(qa[ak][2]), "r"(qa[ak][3]),
                      "r"(bfr[nt][0]), "r"(bfr[nt][1]));
            }
        }

        #pragma unroll
        for (int i = 0; i < 2; i++)
            *(uint4*)&V3s[vr[i]*VST + vblk[i]*16 + vc[i]*4] = vreg[i];

        float mx0 = fmaxf(fmaxf(sc[0][0], sc[0][1]), fmaxf(sc[1][0], sc[1][1]));
        float mx1 = fmaxf(fmaxf(sc[0][2], sc[0][3]), fmaxf(sc[1][2], sc[1][3]));
        mx0 = fmaxf(mx0, __shfl_xor_sync(0xFFFFFFFFu, mx0, 1));
        mx0 = fmaxf(mx0, __shfl_xor_sync(0xFFFFFFFFu, mx0, 2));
        mx1 = fmaxf(mx1, __shfl_xor_sync(0xFFFFFFFFu, mx1, 1));
        mx1 = fmaxf(mx1, __shfl_xor_sync(0xFFFFFFFFu, mx1, 2));
        if (t == 0) { pmax[r0][wn] = mx0; pmax[r1][wn] = mx1; }
        __syncthreads();   // sync_A

        if (k0 + 32 < SQ) {
            #pragma unroll
            for (int i = 0; i < 2; i++)
                asm volatile("cp.async.cg.shared.global [%0], [%1], 16;\n"
                             :: "r"(sK + (kr[i]*QST + kc[i]*4)*4),
                                "l"(Kg + (size_t)(k0 + 32 + kr[i])*128 + kc[i]*8));
            asm volatile("cp.async.commit_group;\n");
        }

        float mold0 = mrow[r0], mold1 = mrow[r1];
        float lold0 = lrow[r0], lold1 = lrow[r1];
        float M0 = fmaxf(fmaxf(pmax[r0][0], pmax[r0][1]), mold0);
        float M1 = fmaxf(fmaxf(pmax[r1][0], pmax[r1][1]), mold1);
        float al0 = __expf(mold0 - M0);
        float al1 = __expf(mold1 - M1);
        float s0 = 0.f, s1 = 0.f;
        #pragma unroll
        for (int nt = 0; nt < 2; nt++) {
            float p0 = __expf(sc[nt][0] - M0);
            float p1 = __expf(sc[nt][1] - M0);
            float p2 = __expf(sc[nt][2] - M1);
            float p3 = __expf(sc[nt][3] - M1);
            s0 += p0 + p1; s1 += p2 + p3;
            int c = wn*16 + nt*8 + 2*t;
            __nv_bfloat16 h0 = __float2bfloat16(p0);
            __nv_bfloat16 l0 = __float2bfloat16(p0 - __bfloat162float(h0));
            __nv_bfloat16 h1 = __float2bfloat16(p1);
            __nv_bfloat16 l1 = __float2bfloat16(p1 - __bfloat162float(h1));
            __nv_bfloat16 h2 = __float2bfloat16(p2);
            __nv_bfloat16 l2 = __float2bfloat16(p2 - __bfloat162float(h2));
            __nv_bfloat16 h3 = __float2bfloat16(p3);
            __nv_bfloat16 l3 = __float2bfloat16(p3 - __bfloat162float(h3));
            // P3 = [Ph | Pl] (72 bf16 stride)
            *(__nv_bfloat162*)&P3h[r0*72 + c]      = __nv_bfloat162(h0, h1);
            *(__nv_bfloat162*)&P3h[r0*72 + 32 + c] = __nv_bfloat162(l0, l1);
            *(__nv_bfloat162*)&P3h[r1*72 + c]      = __nv_bfloat162(h2, h3);
            *(__nv_bfloat162*)&P3h[r1*72 + 32 + c] = __nv_bfloat162(l2, l3);
        }
        s0 += __shfl_xor_sync(0xFFFFFFFFu, s0, 1);
        s0 += __shfl_xor_sync(0xFFFFFFFFu, s0, 2);
        s1 += __shfl_xor_sync(0xFFFFFFFFu, s1, 1);
        s1 += __shfl_xor_sync(0xFFFFFFFFu, s1, 2);
        if (t == 0) { psum[r0][wn] = s0; psum[r1][wn] = s1; }
        __syncthreads();   // sync_B

        if (wn == 0 && t == 0) {
            lrow[r0] = lold0*al0 + psum[r0][0] + psum[r0][1];
            lrow[r1] = lold1*al1 + psum[r1][0] + psum[r1][1];
            mrow[r0] = M0;
            mrow[r1] = M1;
        }

        // --- O: Ph.Vh + Ph.Vl + Pl.Vh ---
        #pragma unroll
        for (int nt = 0; nt < 4; nt++) {
            o[nt][0] *= al0; o[nt][1] *= al0;
            o[nt][2] *= al1; o[nt][3] *= al1;
        }
        const int paI[6] = {0,1, 0,1, 2,3};
        const int vbI[6] = {0,1, 2,3, 0,1};
        #pragma unroll
        for (int it = 0; it < 6; it++) {
            int pk = paI[it], vk = vbI[it];
            uint32_t pa[4], vb[4][2];
            int ar = (wm*16 + g)*VST + pk*8 + t;
            pa[0] = P3s[ar];
            pa[1] = P3s[ar + 8*VST];
            pa[2] = P3s[ar + 4];
            pa[3] = P3s[ar + 8*VST + 4];
            #pragma unroll
            for (int nt = 0; nt < 4; nt++) {
                int br = (wn*32 + nt*8 + g)*VST + vk*8 + t;
                vb[nt][0] = V3s[br];
                vb[nt][1] = V3s[br + 4];
            }
            #pragma unroll
            for (int nt = 0; nt < 4; nt++) {
                asm volatile(
                    "mma.sync.aligned.m16n8k16.row.col.f32.bf16.bf16.f32 "
                    "{%0,%1,%2,%3}, {%4,%5,%6,%7}, {%8,%9}, {%0,%1,%2,%3};"
                    : "+f"(o[nt][0]), "+f"(o[nt][1]), "+f"(o[nt][2]), "+f"(o[nt][3])
                    : "r"(pa[0]), "r"(pa[1]), "r"(pa[2]), "r"(pa[3]),
                      "r"(vb[nt][0]), "r"(vb[nt][1]));
            }
        }
    }

    __syncthreads();

    // epilogue: normalize + split-write g_o3 ([h|h|l] over DM), packed bf16x2
    int b = blockIdx.z, h = blockIdx.y;
    float i0 = 1.f / lrow[r0];
    float i1 = 1.f / lrow[r1];
    size_t b0 = (size_t)(b*SQ + q0 + r0)*K3;
    size_t b1 = (size_t)(b*SQ + q0 + r1)*K3;
    #pragma unroll
    for (int nt = 0; nt < 4; nt++) {
        int col = h*64 + wn*32 + nt*8 + 2*t;
        float v00 = o[nt][0] * i0, v01 = o[nt][1] * i0;
        float v10 = o[nt][2] * i1, v11 = o[nt][3] * i1;
        __nv_bfloat16 h00 = __float2bfloat16(v00);
        __nv_bfloat16 l00 = __float2bfloat16(v00 - __bfloat162float(h00));
        __nv_bfloat16 h01 = __float2bfloat16(v01);
        __nv_bfloat16 l01 = __float2bfloat16(v01 - __bfloat162float(h01));
        __nv_bfloat16 h10 = __float2bfloat16(v10);
        __nv_bfloat16 l10 = __float2bfloat16(v10 - __bfloat162float(h10));
        __nv_bfloat16 h11 = __float2bfloat16(v11);
        __nv_bfloat16 l11 = __float2bfloat16(v11 - __bfloat162float(h11));
        __nv_bfloat162 hp0 = __nv_bfloat162(h00, h01);
        __nv_bfloat162 lp0 = __nv_bfloat162(l00, l01);
        __nv_bfloat162 hp1 = __nv_bfloat162(h10, h11);
        __nv_bfloat162 lp1 = __nv_bfloat162(l10, l11);
        *(__nv_bfloat162*)&g_o3[b0 + col]        = hp0;
        *(__nv_bfloat162*)&g_o3[b0 + DM + col]   = hp0;
        *(__nv_bfloat162*)&g_o3[b0 + 2*DM + col] = lp0;
        *(__nv_bfloat162*)&g_o3[b1 + col]        = hp1;
        *(__nv_bfloat162*)&g_o3[b1 + DM + col]   = hp1;
        *(__nv_bfloat162*)&g_o3[b1 + 2*DM + col] = lp1;
    }
}

extern "C" void kernel_launch(void* const* d_in, const int* in_sizes, int n_in,
                              void* d_out, int out_size)
{
    const float* x  = (const float*)d_in[0];
    const float* wq = (const float*)d_in[1];
    const float* bq = (const float*)d_in[2];
    const float* wk = (const float*)d_in[3];
    const float* bk = (const float*)d_in[4];
    const float* wv = (const float*)d_in[5];
    const float* bv = (const float*)d_in[6];
    const float* wo = (const float*)d_in[7];
    const float* bo = (const float*)d_in[8];
    float* out = (float*)d_out;

    float *v;
    __nv_bfloat16 *x3, *o3, *wq3, *wk3, *wv3, *wo3, *q3, *k3;
    cudaGetSymbolAddress((void**)&v, g_v);
    cudaGetSymbolAddress((void**)&x3, g_x3);
    cudaGetSymbolAddress((void**)&o3, g_o3);
    cudaGetSymbolAddress((void**)&wq3, g_wq3);
    cudaGetSymbolAddress((void**)&wk3, g_wk3);
    cudaGetSymbolAddress((void**)&wv3, g_wv3);
    cudaGetSymbolAddress((void**)&wo3, g_wo3);
    cudaGetSymbolAddress((void**)&q3, g_q3);
    cudaGetSymbolAddress((void**)&k3, g_k3);

    int eb = (MR*DM + 255)/256;
    dim3 tb(DM/32, DM/32);
    dim3 gg(DM/128, MR/128);

    expand_a3<<<eb, 256>>>(x, x3, MR, DM);
    expand_b3t<<<tb, 256>>>(wq, wq3, DM, DM);
    expand_b3t<<<tb, 256>>>(wk, wk3, DM, DM);
    expand_b3t<<<tb, 256>>>(wv, wv3, DM, DM);
    gemm_bf16<<<gg, 256>>>(x3, wq3, bq, q3, MR, DM, K3, 1);
    gemm_bf16<<<gg, 256>>>(x3, wk3, bk, k3, MR, DM, K3, 2);
    gemm_bf16<<<gg, 256>>>(x3, wv3, bv, v,  MR, DM, K3, 0);

    expand_v3t<<<dim3(SQ/32, HD/32, BZ*HH), 256>>>(v);

    attn_mma<<<dim3(SQ/64, HH, BZ), 256>>>();

    expand_b3t<<<tb, 256>>>(wo, wo3, DM, DM);
    gemm_bf16<<<gg, 256>>>(o3, wo3, bo, out, MR, DM, K3, 0);
}